// round 1
// baseline (speedup 1.0000x reference)
#include <cuda_runtime.h>
#include <math.h>

#define BB 32
#define SS 8192
#define DD 256
#define CC 512              // 2*D
#define NSPLIT 32
#define RPS (SS / NSPLIT)   // 256 rows per split block
#define TR 16               // tile rows staged in smem
#define NTHREADS 256

// ---------------- scratch (device globals; no allocation allowed) -------------
__device__ __align__(16) float g_u[CC];
__device__ float g_qv[BB];
__device__ float g_pacc[BB][NSPLIT][CC];   // 2 MB partial weighted sums
__device__ float g_pm[BB][NSPLIT];
__device__ float g_pl[BB][NSPLIT];
__device__ float g_mfin[BB];
__device__ float g_lfin[BB];

__device__ __forceinline__ float warp_sum(float v) {
#pragma unroll
    for (int o = 16; o; o >>= 1) v += __shfl_xor_sync(0xffffffffu, v, o);
    return v;
}
__device__ __forceinline__ float warp_max(float v) {
#pragma unroll
    for (int o = 16; o; o >>= 1) v = fmaxf(v, __shfl_xor_sync(0xffffffffu, v, o));
    return v;
}

// ---------------- kernel 1: u = Ua^T va ; qv[b] = va . (Wa @ input[b]) --------
__global__ void prep_kernel(const float* __restrict__ inp,
                            const float* __restrict__ Wa,
                            const float* __restrict__ Ua,
                            const float* __restrict__ va) {
    const int blk = blockIdx.x;
    const int tid = threadIdx.x;
    if (blk < 16) {
        // u columns [32*blk, 32*blk+32); 8 d-groups x 32 cols
        const int c = blk * 32 + (tid & 31);
        const int g = tid >> 5;  // 0..7
        float s = 0.f;
#pragma unroll 8
        for (int i = 0; i < 32; i++) {
            int d = g * 32 + i;
            s += va[d] * Ua[d * CC + c];
        }
        __shared__ float part[8][32];
        part[g][tid & 31] = s;
        __syncthreads();
        if (tid < 32) {
            float t = 0.f;
#pragma unroll
            for (int gg = 0; gg < 8; gg++) t += part[gg][tid];
            g_u[blk * 32 + tid] = t;
        }
    } else {
        // qv[b] : one block per batch. thread t: inp[b,t] * (sum_e va[e]*Wa[e,t])
        const int b = blk - 16;
        __shared__ float va_s[DD];
        __shared__ float red[8];
        va_s[tid] = va[tid];
        __syncthreads();
        float w = 0.f;
#pragma unroll 8
        for (int e = 0; e < DD; e++) w += va_s[e] * Wa[e * DD + tid];
        float sv = inp[b * DD + tid] * w;
        sv = warp_sum(sv);
        if ((tid & 31) == 0) red[tid >> 5] = sv;
        __syncthreads();
        if (tid == 0) {
            float t = 0.f;
#pragma unroll
            for (int i = 0; i < 8; i++) t += red[i];
            g_qv[b] = t;
        }
    }
}

// ---------------- kernel 2: single-pass scores + online softmax + weighted sum
__global__ __launch_bounds__(NTHREADS) void main_kernel(
    const float* __restrict__ ctx, const int* __restrict__ lens,
    float* __restrict__ out) {
    const int b = blockIdx.y, split = blockIdx.x;
    const int tid = threadIdx.x;
    const int warp = tid >> 5, lane = tid & 31;
    const int start = split * RPS;
    const int len = lens[b];
    int nvalid = len - start;
    if (nvalid > RPS) nvalid = RPS;

    __shared__ __align__(16) float tile[TR][CC];
    __shared__ float sc[TR];
    __shared__ float p[TR];
    __shared__ float red2[2];

    const float NEG_INF = __int_as_float(0xff800000);
    float m_run = NEG_INF, l_run = 0.f;
    float2 acc = make_float2(0.f, 0.f);
    const int c0 = tid * 2;
    float* out_align = out + BB * CC;  // raw scores staged in the align region

    if (nvalid > 0) {
        // this lane always touches cols lane*4 + 128*j .. +3 in phase A
        float4 u4[4];
#pragma unroll
        for (int j = 0; j < 4; j++)
            u4[j] = *reinterpret_cast<const float4*>(&g_u[lane * 4 + 128 * j]);
        const float qvb = g_qv[b];
        const float* base = ctx + ((long long)b * SS + start) * CC;

        for (int t0 = 0; t0 < nvalid; t0 += TR) {
            const int nt = min(TR, nvalid - t0);
            // ---- phase A: load tile (single gmem read), dot with u ----
#pragma unroll
            for (int r = warp; r < TR; r += 8) {
                if (r < nt) {
                    const float4* row =
                        reinterpret_cast<const float4*>(base + (long long)(t0 + r) * CC);
                    float dot = 0.f;
#pragma unroll
                    for (int j = 0; j < 4; j++) {
                        float4 v = row[lane + 32 * j];
                        *reinterpret_cast<float4*>(&tile[r][(lane + 32 * j) * 4]) = v;
                        dot += v.x * u4[j].x + v.y * u4[j].y + v.z * u4[j].z + v.w * u4[j].w;
                    }
                    dot = warp_sum(dot);
                    if (lane == 0) {
                        float s = dot + qvb;
                        sc[r] = s;
                        out_align[(long long)b * SS + start + t0 + r] = s;  // raw score
                    }
                } else {
                    float4 z = make_float4(0.f, 0.f, 0.f, 0.f);
#pragma unroll
                    for (int j = 0; j < 4; j++)
                        *reinterpret_cast<float4*>(&tile[r][(lane + 32 * j) * 4]) = z;
                    if (lane == 0) sc[r] = NEG_INF;
                }
            }
            __syncthreads();
            // ---- online softmax bookkeeping (warp 0) ----
            if (warp == 0) {
                float s = (lane < TR) ? sc[lane] : NEG_INF;
                float m = warp_max(s);
                float m_new = fmaxf(m_run, m);
                float pe = (lane < TR) ? __expf(s - m_new) : 0.f;
                if (lane < TR) p[lane] = pe;
                float sum = warp_sum(pe);
                if (lane == 0) { red2[0] = m_new; red2[1] = sum; }
            }
            __syncthreads();
            float m_new = red2[0];
            float scale = __expf(m_run - m_new);  // 0 on first tile (m_run=-inf)
            acc.x *= scale; acc.y *= scale;
            l_run = l_run * scale + red2[1];
            m_run = m_new;
            // ---- phase B: weighted accumulate from smem ----
#pragma unroll
            for (int r = 0; r < TR; r++) {
                float w = p[r];
                float2 t = *reinterpret_cast<const float2*>(&tile[r][c0]);
                acc.x += w * t.x;
                acc.y += w * t.y;
            }
            __syncthreads();
        }
    }
    g_pacc[b][split][c0]     = acc.x;
    g_pacc[b][split][c0 + 1] = acc.y;
    if (tid == 0) { g_pm[b][split] = m_run; g_pl[b][split] = l_run; }
}

// ---------------- kernel 3: combine splits, write attn_h ----------------------
__global__ void reduce_kernel(float* __restrict__ out) {
    const int b = blockIdx.x;
    const int tid = threadIdx.x;
    __shared__ float w_s[NSPLIT];
    __shared__ float lfin_s;
    if (tid < 32) {
        float m = g_pm[b][tid];
        float l = g_pl[b][tid];
        float meff = (l > 0.f) ? m : __int_as_float(0xff800000);
        float m_fin = warp_max(meff);
        float w = (l > 0.f) ? __expf(m - m_fin) : 0.f;
        float l_fin = warp_sum(l * w);
        w_s[tid] = w;
        if (tid == 0) { lfin_s = l_fin; g_mfin[b] = m_fin; g_lfin[b] = l_fin; }
    }
    __syncthreads();
    float inv_l = 1.f / lfin_s;
#pragma unroll
    for (int k = 0; k < 2; k++) {
        int c = tid + k * 256;
        float a = 0.f;
#pragma unroll
        for (int i = 0; i < NSPLIT; i++) a += g_pacc[b][i][c] * w_s[i];
        out[b * CC + c] = a * inv_l;  // attn_h [1,B,2D] flat
    }
}

// ---------------- kernel 4: normalize raw scores -> align_vectors -------------
__global__ void norm_kernel(const int* __restrict__ lens, float* __restrict__ out) {
    int idx = blockIdx.x * blockDim.x + threadIdx.x;  // 0 .. B*S-1
    int b = idx >> 13;       // / 8192
    int s = idx & (SS - 1);
    float* a = out + BB * CC;
    float v = 0.f;
    if (s < lens[b]) {
        float m = g_mfin[b];
        float inv_l = 1.f / g_lfin[b];
        v = __expf(a[idx] - m) * inv_l;
    }
    a[idx] = v;
}

// ---------------- launch -------------------------------------------------------
extern "C" void kernel_launch(void* const* d_in, const int* in_sizes, int n_in,
                              void* d_out, int out_size) {
    const float *inp = nullptr, *ctx = nullptr, *Wa = nullptr, *Ua = nullptr, *va = nullptr;
    const int* lens = nullptr;
    for (int i = 0; i < n_in; i++) {
        switch (in_sizes[i]) {
            case BB * DD:            inp  = (const float*)d_in[i]; break;  // 8192
            case BB * SS * CC:       ctx  = (const float*)d_in[i]; break;  // 134217728
            case DD * DD:            Wa   = (const float*)d_in[i]; break;  // 65536
            case DD * CC:            Ua   = (const float*)d_in[i]; break;  // 131072
            case DD:                 va   = (const float*)d_in[i]; break;  // 256
            case BB:                 lens = (const int*)d_in[i];   break;  // 32
            default: break;
        }
    }
    float* out = (float*)d_out;

    prep_kernel<<<48, 256>>>(inp, Wa, Ua, va);
    dim3 g2(NSPLIT, BB);
    main_kernel<<<g2, NTHREADS>>>(ctx, lens, out);
    reduce_kernel<<<BB, 256>>>(out);
    norm_kernel<<<(BB * SS) / 256, 256>>>(lens, out);
}

// round 2
// speedup vs baseline: 1.0579x; 1.0579x over previous
#include <cuda_runtime.h>
#include <math.h>
#include <stdint.h>

#define BB 32
#define SS 8192
#define DD 256
#define CC 512              // 2*D
#define NSPLIT 16
#define RPS (SS / NSPLIT)   // 512 rows per split block
#define TR 16               // tile rows staged in smem
#define NTHREADS 256
#define TILE_F (TR * CC)    // 8192 floats = 32KB
#define SMEM_BYTES (2 * TILE_F * 4)  // 64KB double buffer

// ---------------- scratch (device globals; no allocation allowed) -------------
__device__ __align__(16) float g_u[CC];
__device__ float g_qv[BB];
__device__ float g_pacc[BB][NSPLIT][CC];
__device__ float g_pm[BB][NSPLIT];
__device__ float g_pl[BB][NSPLIT];
__device__ float g_mfin[BB];
__device__ float g_lfin[BB];

__device__ __forceinline__ float warp_sum(float v) {
#pragma unroll
    for (int o = 16; o; o >>= 1) v += __shfl_xor_sync(0xffffffffu, v, o);
    return v;
}
__device__ __forceinline__ float warp_max(float v) {
#pragma unroll
    for (int o = 16; o; o >>= 1) v = fmaxf(v, __shfl_xor_sync(0xffffffffu, v, o));
    return v;
}

__device__ __forceinline__ void cp_async16(uint32_t saddr, const void* gptr, int src_size) {
    asm volatile("cp.async.cg.shared.global [%0], [%1], 16, %2;\n"
                 :: "r"(saddr), "l"(gptr), "r"(src_size));
}
__device__ __forceinline__ void cp_commit() {
    asm volatile("cp.async.commit_group;\n");
}
template <int N>
__device__ __forceinline__ void cp_wait() {
    asm volatile("cp.async.wait_group %0;\n" :: "n"(N));
}

// ---------------- kernel 1: u = Ua^T va ; qv[b] = va . (Wa @ input[b]) --------
__global__ void prep_kernel(const float* __restrict__ inp,
                            const float* __restrict__ Wa,
                            const float* __restrict__ Ua,
                            const float* __restrict__ va) {
    const int blk = blockIdx.x;
    const int tid = threadIdx.x;
    if (blk < 16) {
        const int c = blk * 32 + (tid & 31);
        const int g = tid >> 5;  // 0..7
        float s = 0.f;
#pragma unroll 8
        for (int i = 0; i < 32; i++) {
            int d = g * 32 + i;
            s += va[d] * Ua[d * CC + c];
        }
        __shared__ float part[8][32];
        part[g][tid & 31] = s;
        __syncthreads();
        if (tid < 32) {
            float t = 0.f;
#pragma unroll
            for (int gg = 0; gg < 8; gg++) t += part[gg][tid];
            g_u[blk * 32 + tid] = t;
        }
    } else {
        const int b = blk - 16;
        __shared__ float va_s[DD];
        __shared__ float red[8];
        va_s[tid] = va[tid];
        __syncthreads();
        float w = 0.f;
#pragma unroll 8
        for (int e = 0; e < DD; e++) w += va_s[e] * Wa[e * DD + tid];
        float sv = inp[b * DD + tid] * w;
        sv = warp_sum(sv);
        if ((tid & 31) == 0) red[tid >> 5] = sv;
        __syncthreads();
        if (tid == 0) {
            float t = 0.f;
#pragma unroll
            for (int i = 0; i < 8; i++) t += red[i];
            g_qv[b] = t;
        }
    }
}

// issue one TR x CC tile into buf via cp.async (2048 16B chunks, 8 per thread)
__device__ __forceinline__ void issue_tile(const float* __restrict__ base, int t0,
                                           int nt, float* buf, int tid) {
    uint32_t saddr = (uint32_t)__cvta_generic_to_shared(buf);
    const float* g0 = base + (long long)t0 * CC;
#pragma unroll
    for (int k = 0; k < 8; k++) {
        int chunk = tid + k * 256;       // 0..2047
        int r = chunk >> 7;              // 128 chunks per row
        int sz = (r < nt) ? 16 : 0;
        cp_async16(saddr + chunk * 16, g0 + chunk * 4, sz);
    }
    cp_commit();
}

// ---------------- kernel 2: pipelined scores + online softmax + weighted sum --
__global__ __launch_bounds__(NTHREADS) void main_kernel(
    const float* __restrict__ ctx, const int* __restrict__ lens,
    float* __restrict__ out) {
    extern __shared__ __align__(16) float smem[];  // 2 x TILE_F
    __shared__ float sc[TR];
    __shared__ float p[TR];
    __shared__ float red2[2];

    const int b = blockIdx.y, split = blockIdx.x;
    const int tid = threadIdx.x;
    const int warp = tid >> 5, lane = tid & 31;
    const int start = split * RPS;
    const int len = lens[b];
    int nvalid = len - start;
    if (nvalid > RPS) nvalid = RPS;
    const int c0 = tid * 2;
    const float NEG_INF = __int_as_float(0xff800000);

    if (nvalid <= 0) {
        g_pacc[b][split][c0] = 0.f;
        g_pacc[b][split][c0 + 1] = 0.f;
        if (tid == 0) { g_pm[b][split] = NEG_INF; g_pl[b][split] = 0.f; }
        return;
    }

    const int ntiles = (nvalid + TR - 1) / TR;
    const float* base = ctx + ((long long)b * SS + start) * CC;
    float* out_align = out + BB * CC;

    float4 u4[4];
#pragma unroll
    for (int j = 0; j < 4; j++)
        u4[j] = *reinterpret_cast<const float4*>(&g_u[(lane + 32 * j) * 4]);
    const float qvb = g_qv[b];

    float m_run = NEG_INF, l_run = 0.f;
    float2 acc = make_float2(0.f, 0.f);

    // prologue
    issue_tile(base, 0, min(TR, nvalid), smem, tid);

    for (int t = 0; t < ntiles; t++) {
        const int t0 = t * TR;
        const int nt = min(TR, nvalid - t0);
        if (t + 1 < ntiles) {
            issue_tile(base, (t + 1) * TR, min(TR, nvalid - (t + 1) * TR),
                       smem + ((t + 1) & 1) * TILE_F, tid);
            cp_wait<1>();
        } else {
            cp_wait<0>();
        }
        __syncthreads();  // tile t visible to all

        float* tile = smem + (t & 1) * TILE_F;

        // ---- phase A: scores from smem (2 rows per warp) ----
#pragma unroll
        for (int rr = 0; rr < 2; rr++) {
            const int r = warp * 2 + rr;
            if (r < nt) {
                const float4* row = reinterpret_cast<const float4*>(tile + r * CC);
                float dot = 0.f;
#pragma unroll
                for (int j = 0; j < 4; j++) {
                    float4 v = row[lane + 32 * j];
                    dot += v.x * u4[j].x + v.y * u4[j].y + v.z * u4[j].z + v.w * u4[j].w;
                }
                dot = warp_sum(dot);
                if (lane == 0) {
                    float s = dot + qvb;
                    sc[r] = s;
                    out_align[(long long)b * SS + start + t0 + r] = s;  // raw score
                }
            } else if (lane == 0) {
                sc[r] = NEG_INF;
            }
        }
        __syncthreads();  // sc ready

        // ---- online softmax bookkeeping (warp 0) ----
        if (warp == 0) {
            float s = (lane < TR) ? sc[lane] : NEG_INF;
            float m = warp_max(s);
            float m_new = fmaxf(m_run, m);
            float pe = (lane < TR) ? __expf(s - m_new) : 0.f;
            if (lane < TR) p[lane] = pe;
            float sum = warp_sum(pe);
            if (lane == 0) { red2[0] = m_new; red2[1] = sum; }
        }
        __syncthreads();  // p, red2 ready

        float m_new = red2[0];
        float scale = __expf(m_run - m_new);  // 0 on first tile
        acc.x *= scale; acc.y *= scale;
        l_run = l_run * scale + red2[1];
        m_run = m_new;

        // ---- phase B: weighted accumulate from smem ----
#pragma unroll
        for (int r = 0; r < TR; r++) {
            float w = p[r];
            float2 tv = *reinterpret_cast<const float2*>(&tile[r * CC + c0]);
            acc.x += w * tv.x;
            acc.y += w * tv.y;
        }
        __syncthreads();  // done with tile & sc before buffer reuse
    }

    g_pacc[b][split][c0]     = acc.x;
    g_pacc[b][split][c0 + 1] = acc.y;
    if (tid == 0) { g_pm[b][split] = m_run; g_pl[b][split] = l_run; }
}

// ---------------- kernel 3: combine splits, write attn_h ----------------------
__global__ void reduce_kernel(float* __restrict__ out) {
    const int b = blockIdx.x;
    const int tid = threadIdx.x;
    __shared__ float w_s[NSPLIT];
    __shared__ float lfin_s;
    if (tid < 32) {
        float m = (tid < NSPLIT) ? g_pm[b][tid] : __int_as_float(0xff800000);
        float l = (tid < NSPLIT) ? g_pl[b][tid] : 0.f;
        float meff = (l > 0.f) ? m : __int_as_float(0xff800000);
        float m_fin = warp_max(meff);
        float w = (l > 0.f) ? __expf(m - m_fin) : 0.f;
        float l_fin = warp_sum(l * w);
        if (tid < NSPLIT) w_s[tid] = w;
        if (tid == 0) { lfin_s = l_fin; g_mfin[b] = m_fin; g_lfin[b] = l_fin; }
    }
    __syncthreads();
    float inv_l = 1.f / lfin_s;
#pragma unroll
    for (int k = 0; k < 2; k++) {
        int c = tid + k * 256;
        float a = 0.f;
#pragma unroll
        for (int i = 0; i < NSPLIT; i++) a += g_pacc[b][i][c] * w_s[i];
        out[b * CC + c] = a * inv_l;
    }
}

// ---------------- kernel 4: normalize raw scores -> align_vectors (float4) ----
__global__ void norm_kernel(const int* __restrict__ lens, float* __restrict__ out) {
    int i4 = blockIdx.x * blockDim.x + threadIdx.x;  // 0 .. B*S/4-1
    float4* a = reinterpret_cast<float4*>(out + BB * CC);
    int b = i4 >> 11;            // 2048 float4 per batch row
    int s = (i4 & 2047) << 2;
    int len = lens[b];
    float m = g_mfin[b];
    float inv_l = 1.f / g_lfin[b];
    float4 v = a[i4];
    v.x = (s + 0 < len) ? __expf(v.x - m) * inv_l : 0.f;
    v.y = (s + 1 < len) ? __expf(v.y - m) * inv_l : 0.f;
    v.z = (s + 2 < len) ? __expf(v.z - m) * inv_l : 0.f;
    v.w = (s + 3 < len) ? __expf(v.w - m) * inv_l : 0.f;
    a[i4] = v;
}

// ---------------- launch -------------------------------------------------------
extern "C" void kernel_launch(void* const* d_in, const int* in_sizes, int n_in,
                              void* d_out, int out_size) {
    const float *inp = nullptr, *ctx = nullptr, *Wa = nullptr, *Ua = nullptr, *va = nullptr;
    const int* lens = nullptr;
    for (int i = 0; i < n_in; i++) {
        switch (in_sizes[i]) {
            case BB * DD:            inp  = (const float*)d_in[i]; break;
            case BB * SS * CC:       ctx  = (const float*)d_in[i]; break;
            case DD * DD:            Wa   = (const float*)d_in[i]; break;
            case DD * CC:            Ua   = (const float*)d_in[i]; break;
            case DD:                 va   = (const float*)d_in[i]; break;
            case BB:                 lens = (const int*)d_in[i];   break;
            default: break;
        }
    }
    float* out = (float*)d_out;

    cudaFuncSetAttribute(main_kernel, cudaFuncAttributeMaxDynamicSharedMemorySize,
                         SMEM_BYTES);

    prep_kernel<<<48, 256>>>(inp, Wa, Ua, va);
    dim3 g2(NSPLIT, BB);
    main_kernel<<<g2, NTHREADS, SMEM_BYTES>>>(ctx, lens, out);
    reduce_kernel<<<BB, 256>>>(out);
    norm_kernel<<<(BB * SS) / 4 / 256, 256>>>(lens, out);
}